// round 1
// baseline (speedup 1.0000x reference)
#include <cuda_runtime.h>

#define BATCH   512
#define SEQ     176
#define DIN     128
#define NH      8
#define HD      64
#define DMODEL  512
#define NEGV    (-9e15f)

#define M_TOTAL (BATCH * SEQ)          // 90112
#define M_BLK   64
#define KT_STRIDE 177

// scratch: [B, H, S, D] each (allowed via __device__ globals)
static __device__ float g_Q[(size_t)BATCH * NH * SEQ * HD];
static __device__ float g_K[(size_t)BATCH * NH * SEQ * HD];
static __device__ float g_V[(size_t)BATCH * NH * SEQ * HD];

// ---------------------------------------------------------------------------
// Kernel A: fused QKV projection. Grid: (M_TOTAL/64, NH). Block: 256 threads.
// Each block computes a 64-row x 64-col (= one head) tile of Q, K, V,
// reusing the x tile for all three weight matrices.
// ---------------------------------------------------------------------------
__global__ void qkv_kernel(const float* __restrict__ x,
                           const float* __restrict__ Wq, const float* __restrict__ bq,
                           const float* __restrict__ Wk, const float* __restrict__ bk,
                           const float* __restrict__ Wv, const float* __restrict__ bv)
{
    __shared__ float xs[64 * 16];
    __shared__ float wsq[16 * 64];
    __shared__ float wsk[16 * 64];
    __shared__ float wsv[16 * 64];

    const int tid  = threadIdx.x;
    const int mblk = blockIdx.x;
    const int h    = blockIdx.y;
    const int m0   = mblk * M_BLK;
    const int ty   = tid >> 4;     // 0..15 -> 4 rows each
    const int tx   = tid & 15;     // 0..15 -> 4 cols each

    float aq[4][4] = {};
    float ak[4][4] = {};
    float av[4][4] = {};

    // loader mappings
    const int lrow = tid >> 2;     // 0..63
    const int lc4  = tid & 3;      // 0..3  (x: 4 float4 per row)
    const int wkr  = tid >> 4;     // 0..15
    const int wc4  = tid & 15;     // 0..15 (W: 16 float4 per row)

    for (int k0 = 0; k0 < DIN; k0 += 16) {
        __syncthreads();
        // x tile: [64 rows, 16 k]
        *(float4*)(xs + lrow * 16 + lc4 * 4) =
            *(const float4*)(x + (size_t)(m0 + lrow) * DIN + k0 + lc4 * 4);
        // W tiles: [16 k, 64 n] for head h
        const size_t woff = (size_t)(k0 + wkr) * DMODEL + h * HD + wc4 * 4;
        *(float4*)(wsq + wkr * 64 + wc4 * 4) = *(const float4*)(Wq + woff);
        *(float4*)(wsk + wkr * 64 + wc4 * 4) = *(const float4*)(Wk + woff);
        *(float4*)(wsv + wkr * 64 + wc4 * 4) = *(const float4*)(Wv + woff);
        __syncthreads();

        #pragma unroll
        for (int kk = 0; kk < 16; kk++) {
            float a[4];
            #pragma unroll
            for (int i = 0; i < 4; i++) a[i] = xs[(ty * 4 + i) * 16 + kk];
            float4 bq4 = *(const float4*)(wsq + kk * 64 + tx * 4);
            float4 bk4 = *(const float4*)(wsk + kk * 64 + tx * 4);
            float4 bv4 = *(const float4*)(wsv + kk * 64 + tx * 4);
            #pragma unroll
            for (int i = 0; i < 4; i++) {
                aq[i][0] += a[i] * bq4.x; aq[i][1] += a[i] * bq4.y;
                aq[i][2] += a[i] * bq4.z; aq[i][3] += a[i] * bq4.w;
                ak[i][0] += a[i] * bk4.x; ak[i][1] += a[i] * bk4.y;
                ak[i][2] += a[i] * bk4.z; ak[i][3] += a[i] * bk4.w;
                av[i][0] += a[i] * bv4.x; av[i][1] += a[i] * bv4.y;
                av[i][2] += a[i] * bv4.z; av[i][3] += a[i] * bv4.w;
            }
        }
    }

    // epilogue: bias (+ReLU for V), write to [B,H,S,D] scratch
    const float4 biasq = *(const float4*)(bq + h * HD + tx * 4);
    const float4 biask = *(const float4*)(bk + h * HD + tx * 4);
    const float4 biasv = *(const float4*)(bv + h * HD + tx * 4);

    #pragma unroll
    for (int i = 0; i < 4; i++) {
        const int m = m0 + ty * 4 + i;
        const int b = m / SEQ;
        const int s = m - b * SEQ;
        const size_t base = ((size_t)(b * NH + h) * SEQ + s) * HD + tx * 4;
        float4 q, k, v;
        q.x = aq[i][0] + biasq.x; q.y = aq[i][1] + biasq.y;
        q.z = aq[i][2] + biasq.z; q.w = aq[i][3] + biasq.w;
        k.x = ak[i][0] + biask.x; k.y = ak[i][1] + biask.y;
        k.z = ak[i][2] + biask.z; k.w = ak[i][3] + biask.w;
        v.x = fmaxf(av[i][0] + biasv.x, 0.f); v.y = fmaxf(av[i][1] + biasv.y, 0.f);
        v.z = fmaxf(av[i][2] + biasv.z, 0.f); v.w = fmaxf(av[i][3] + biasv.w, 0.f);
        *(float4*)(g_Q + base) = q;
        *(float4*)(g_K + base) = k;
        *(float4*)(g_V + base) = v;
    }
}

// ---------------------------------------------------------------------------
// Kernel B: attention. Grid: B*NH blocks, 256 threads (8 warps).
// Warp w owns query rows [w*22, w*22+22), processed in chunks of 8.
// Lane owns key columns j = lane + 32*t, t in [0,6).
// ---------------------------------------------------------------------------
#define KT_ELEMS (64 * KT_STRIDE + 64)   // + pad so j up to 191 stays in-bounds
#define SMEM2_FLOATS (KT_ELEMS + SEQ*HD + SEQ*HD + 8*8*SEQ)
#define SMEM2_BYTES  (SMEM2_FLOATS * 4)

__global__ void attn_kernel(float* __restrict__ out)
{
    extern __shared__ float sm[];
    float* KT = sm;                       // [64][177] (+pad)
    float* Vs = KT + KT_ELEMS;            // [176][64]
    float* Qs = Vs + SEQ * HD;            // [176][64]
    float* pb = Qs + SEQ * HD;            // [8 warps][8 rows][176]

    const int tid = threadIdx.x;
    const int bh  = blockIdx.x;
    const int b   = bh >> 3;
    const int h   = bh & 7;

    const float* qg = g_Q + (size_t)bh * SEQ * HD;
    const float* kg = g_K + (size_t)bh * SEQ * HD;
    const float* vg = g_V + (size_t)bh * SEQ * HD;

    // load Q, V (vectorized), K transposed (conflict-free: stride 177, 17 odd)
    for (int i = tid; i < SEQ * HD / 4; i += 256) {
        ((float4*)Qs)[i] = ((const float4*)qg)[i];
        ((float4*)Vs)[i] = ((const float4*)vg)[i];
    }
    for (int i = tid; i < SEQ * HD; i += 256) {
        const int s = i >> 6, d = i & 63;
        KT[d * KT_STRIDE + s] = kg[i];
    }
    __syncthreads();

    const int w    = tid >> 5;
    const int lane = tid & 31;
    const float scale = 0.125f;   // 1/sqrt(64)

    // per-lane key column metadata
    int   jv[6];
    int   kf[6];
    #pragma unroll
    for (int t = 0; t < 6; t++) { jv[t] = lane + 32 * t; kf[t] = jv[t] / 22; }

    for (int c = 0; c < 3; c++) {
        const int rbase = w * 22 + c * 8;
        const int nrows = (c == 2) ? 6 : 8;
        int rows[8];
        #pragma unroll
        for (int r = 0; r < 8; r++) {
            int rr = rbase + r;
            rows[r] = rr < SEQ ? rr : SEQ - 1;   // clamp (dupes harmless)
        }

        // ---- scores: acc[r][t] = q_row . k_j ----
        float acc[8][6];
        #pragma unroll
        for (int r = 0; r < 8; r++)
            #pragma unroll
            for (int t = 0; t < 6; t++) acc[r][t] = 0.f;

        for (int d = 0; d < HD; d++) {
            float kt[6];
            #pragma unroll
            for (int t = 0; t < 6; t++) kt[t] = KT[d * KT_STRIDE + jv[t]];
            #pragma unroll
            for (int r = 0; r < 8; r++) {
                const float q = Qs[rows[r] * HD + d];
                #pragma unroll
                for (int t = 0; t < 6; t++) acc[r][t] += q * kt[t];
            }
        }

        // ---- mask + softmax (unnormalized) ----
        float inv[8];
        #pragma unroll
        for (int r = 0; r < 8; r++) {
            const int row = rows[r];
            const int fq  = row / 22;
            #pragma unroll
            for (int t = 0; t < 6; t++) {
                const bool masked = (jv[t] >= SEQ) || (kf[t] == fq && jv[t] != row);
                acc[r][t] = masked ? NEGV : acc[r][t] * scale;
            }
            float m = acc[r][0];
            #pragma unroll
            for (int t = 1; t < 6; t++) m = fmaxf(m, acc[r][t]);
            #pragma unroll
            for (int off = 16; off > 0; off >>= 1)
                m = fmaxf(m, __shfl_xor_sync(0xffffffffu, m, off));
            float ssum = 0.f;
            #pragma unroll
            for (int t = 0; t < 6; t++) {
                const float e = __expf(acc[r][t] - m);
                acc[r][t] = e;
                ssum += e;
            }
            #pragma unroll
            for (int off = 16; off > 0; off >>= 1)
                ssum += __shfl_xor_sync(0xffffffffu, ssum, off);
            inv[r] = 1.0f / ssum;
            #pragma unroll
            for (int t = 0; t < 6; t++)
                if (jv[t] < SEQ) pb[(w * 8 + r) * SEQ + jv[t]] = acc[r][t];
        }
        __syncwarp();

        // ---- PV: each lane owns d = lane and d = lane+32 ----
        float o0[8] = {}, o1[8] = {};
        for (int j = 0; j < SEQ; j++) {
            const float v0 = Vs[j * HD + lane];
            const float v1 = Vs[j * HD + lane + 32];
            #pragma unroll
            for (int r = 0; r < 8; r++) {
                const float p = pb[(w * 8 + r) * SEQ + j];
                o0[r] += p * v0;
                o1[r] += p * v1;
            }
        }

        #pragma unroll
        for (int r = 0; r < 8; r++) {
            if (r < nrows) {
                const int row = rbase + r;
                const size_t oidx = ((size_t)b * SEQ + row) * DMODEL + h * HD + lane;
                out[oidx]      = o0[r] * inv[r];
                out[oidx + 32] = o1[r] * inv[r];
            }
        }
        __syncwarp();   // pb reused next chunk
    }
}

// ---------------------------------------------------------------------------
extern "C" void kernel_launch(void* const* d_in, const int* in_sizes, int n_in,
                              void* d_out, int out_size)
{
    const float* x  = (const float*)d_in[0];
    const float* Wq = (const float*)d_in[1];
    const float* bq = (const float*)d_in[2];
    const float* Wk = (const float*)d_in[3];
    const float* bk = (const float*)d_in[4];
    const float* Wv = (const float*)d_in[5];
    const float* bv = (const float*)d_in[6];
    float* out = (float*)d_out;

    cudaFuncSetAttribute(attn_kernel,
                         cudaFuncAttributeMaxDynamicSharedMemorySize, SMEM2_BYTES);

    qkv_kernel<<<dim3(M_TOTAL / M_BLK, NH), 256>>>(x, Wq, bq, Wk, bk, Wv, bv);
    attn_kernel<<<BATCH * NH, 256, SMEM2_BYTES>>>(out);
}

// round 3
// speedup vs baseline: 1.3635x; 1.3635x over previous
#include <cuda_runtime.h>

#define BATCH   512
#define SEQ     176
#define DIN     128
#define NH      8
#define HD      64
#define DMODEL  512
#define NEGV    (-9e15f)

#define M_TOTAL (BATCH * SEQ)          // 90112

// scratch: [B, H, S, D] each
static __device__ float g_Q[(size_t)BATCH * NH * SEQ * HD];
static __device__ float g_K[(size_t)BATCH * NH * SEQ * HD];
static __device__ float g_V[(size_t)BATCH * NH * SEQ * HD];

// ---------------------------------------------------------------------------
// Kernel A: QKV projection with tf32 mma.sync m16n8k8.
// Grid: (M_TOTAL/256, NH, 3). Block: 256 threads (8 warps).
// Block computes 256 rows x 64 cols (one head) of one matrix (z: 0=Q,1=K,2=V).
// Warp w: rows [w*32, w*32+32) -> 2 m16 tiles x 8 n8 tiles.
// ---------------------------------------------------------------------------
#define SX 20   // xs row stride (floats): conflict-free A-fragment loads
#define SW 72   // ws row stride (floats): conflict-free B-fragment loads

__device__ __forceinline__ unsigned f2tf32(float f) {
    unsigned u;
    asm("cvt.rna.tf32.f32 %0, %1;" : "=r"(u) : "f"(f));
    return u;
}

__device__ __forceinline__ void mma_tf32(float c[4], const unsigned a[4], const unsigned b[2]) {
    asm volatile(
        "mma.sync.aligned.m16n8k8.row.col.f32.tf32.tf32.f32 "
        "{%0,%1,%2,%3}, {%4,%5,%6,%7}, {%8,%9}, {%0,%1,%2,%3};"
        : "+f"(c[0]), "+f"(c[1]), "+f"(c[2]), "+f"(c[3])
        : "r"(a[0]), "r"(a[1]), "r"(a[2]), "r"(a[3]), "r"(b[0]), "r"(b[1]));
}

__global__ void qkv_mma_kernel(const float* __restrict__ x,
                               const float* __restrict__ Wq, const float* __restrict__ bq,
                               const float* __restrict__ Wk, const float* __restrict__ bk,
                               const float* __restrict__ Wv, const float* __restrict__ bv)
{
    __shared__ unsigned xs[256 * SX];
    __shared__ unsigned ws[16 * SW];

    const int z = blockIdx.z;
    const float* W  = (z == 0) ? Wq : (z == 1) ? Wk : Wv;
    const float* bb = (z == 0) ? bq : (z == 1) ? bk : bv;
    float* dst      = (z == 0) ? g_Q : (z == 1) ? g_K : g_V;
    const bool relu = (z == 2);

    const int tid = threadIdx.x;
    const int w    = tid >> 5;
    const int lane = tid & 31;
    const int gid  = lane >> 2;   // 0..7
    const int tig  = lane & 3;    // 0..3

    const int m0 = blockIdx.x * 256;
    const int h  = blockIdx.y;
    const int n0 = h * HD;

    float acc[2][8][4];
    #pragma unroll
    for (int mt = 0; mt < 2; mt++)
        #pragma unroll
        for (int nt = 0; nt < 8; nt++)
            #pragma unroll
            for (int i = 0; i < 4; i++) acc[mt][nt][i] = 0.f;

    // staging maps
    const int xrow = tid >> 2;          // 0..63 (+64*i)
    const int xc4  = (tid & 3) * 4;     // 0,4,8,12
    const int wrow = tid >> 4;          // 0..15
    const int wc4  = (tid & 15) * 4;    // 0..60

    for (int k0 = 0; k0 < DIN; k0 += 16) {
        __syncthreads();
        // stage x (256x16), pre-rounded to tf32
        #pragma unroll
        for (int i = 0; i < 4; i++) {
            const int r = xrow + i * 64;
            float4 v = *(const float4*)(x + (size_t)(m0 + r) * DIN + k0 + xc4);
            unsigned* p = xs + r * SX + xc4;
            p[0] = f2tf32(v.x); p[1] = f2tf32(v.y); p[2] = f2tf32(v.z); p[3] = f2tf32(v.w);
        }
        // stage W (16x64)
        {
            float4 v = *(const float4*)(W + (size_t)(k0 + wrow) * DMODEL + n0 + wc4);
            unsigned* p = ws + wrow * SW + wc4;
            p[0] = f2tf32(v.x); p[1] = f2tf32(v.y); p[2] = f2tf32(v.z); p[3] = f2tf32(v.w);
        }
        __syncthreads();

        #pragma unroll
        for (int kk = 0; kk < 16; kk += 8) {
            unsigned a[2][4];
            #pragma unroll
            for (int mt = 0; mt < 2; mt++) {
                const int r = w * 32 + mt * 16 + gid;
                a[mt][0] = xs[(r    ) * SX + kk + tig];
                a[mt][1] = xs[(r + 8) * SX + kk + tig];
                a[mt][2] = xs[(r    ) * SX + kk + tig + 4];
                a[mt][3] = xs[(r + 8) * SX + kk + tig + 4];
            }
            unsigned b[8][2];
            #pragma unroll
            for (int nt = 0; nt < 8; nt++) {
                b[nt][0] = ws[(kk + tig    ) * SW + nt * 8 + gid];
                b[nt][1] = ws[(kk + tig + 4) * SW + nt * 8 + gid];
            }
            #pragma unroll
            for (int mt = 0; mt < 2; mt++)
                #pragma unroll
                for (int nt = 0; nt < 8; nt++)
                    mma_tf32(acc[mt][nt], a[mt], b[nt]);
        }
    }

    // epilogue: bias (+ReLU for V), write [B,H,S,D]
    float2 bias2[8];
    #pragma unroll
    for (int nt = 0; nt < 8; nt++)
        bias2[nt] = *(const float2*)(bb + n0 + nt * 8 + 2 * tig);

    #pragma unroll
    for (int mt = 0; mt < 2; mt++) {
        #pragma unroll
        for (int half = 0; half < 2; half++) {
            const int m = m0 + w * 32 + mt * 16 + gid + half * 8;
            const int bidx = m / SEQ;
            const int s    = m - bidx * SEQ;
            const size_t base = ((size_t)(bidx * NH + h) * SEQ + s) * HD;
            #pragma unroll
            for (int nt = 0; nt < 8; nt++) {
                float2 o;
                o.x = acc[mt][nt][half * 2 + 0] + bias2[nt].x;
                o.y = acc[mt][nt][half * 2 + 1] + bias2[nt].y;
                if (relu) { o.x = fmaxf(o.x, 0.f); o.y = fmaxf(o.y, 0.f); }
                *(float2*)(dst + base + nt * 8 + 2 * tig) = o;
            }
        }
    }
}

// ---------------------------------------------------------------------------
// Kernel B: attention. Grid: B*NH blocks, 512 threads (16 warps).
// Warp w owns rows [w*11, w*11+11), processed in chunks of 6 (6 + 5).
// Lane owns key pairs j0 = 2*lane + 64*t, t in [0,3).
// Lane owns output dims d = 2*lane, 2*lane+1.
// ---------------------------------------------------------------------------
#define KT_STRIDE 178
#define KT_ELEMS  (64 * KT_STRIDE + 64)
#define PB_ROWS   (16 * 6)
#define SMEM2_FLOATS (KT_ELEMS + SEQ*HD + SEQ*HD + PB_ROWS * SEQ)
#define SMEM2_BYTES  (SMEM2_FLOATS * 4)

__global__ void attn_kernel(float* __restrict__ out)
{
    extern __shared__ float sm[];
    float* KT = sm;                       // [64][178] (+pad)
    float* Vs = KT + KT_ELEMS;            // [176][64]
    float* Qs = Vs + SEQ * HD;            // [176][64]
    float* pb = Qs + SEQ * HD;            // [16 warps][6 rows][176]

    const int tid = threadIdx.x;
    const int bh  = blockIdx.x;
    const int b   = bh >> 3;
    const int h   = bh & 7;

    const float* qg = g_Q + (size_t)bh * SEQ * HD;
    const float* kg = g_K + (size_t)bh * SEQ * HD;
    const float* vg = g_V + (size_t)bh * SEQ * HD;

    for (int i = tid; i < SEQ * HD / 4; i += 512) {
        ((float4*)Qs)[i] = ((const float4*)qg)[i];
        ((float4*)Vs)[i] = ((const float4*)vg)[i];
    }
    for (int i = tid; i < SEQ * HD; i += 512) {
        const int s = i >> 6, d = i & 63;
        KT[d * KT_STRIDE + s] = kg[i];
    }
    __syncthreads();

    const int w    = tid >> 5;
    const int lane = tid & 31;
    const float scale = 0.125f;

    // per-lane key pair metadata
    int j0v[3], jf0[3], jf1[3];
    #pragma unroll
    for (int t = 0; t < 3; t++) {
        j0v[t] = 2 * lane + 64 * t;
        jf0[t] = j0v[t] / 22;
        jf1[t] = (j0v[t] + 1) / 22;
    }

    for (int c = 0; c < 2; c++) {
        const int rbase = w * 11 + c * 6;
        const int nrows = (c == 0) ? 6 : 5;
        int rows[6];
        #pragma unroll
        for (int r = 0; r < 6; r++) {
            int rr = rbase + r;
            rows[r] = (r < nrows) ? rr : rbase;   // clamp dup (guarded on store)
        }

        // ---- scores ----
        float acc[6][3][2];
        #pragma unroll
        for (int r = 0; r < 6; r++)
            #pragma unroll
            for (int t = 0; t < 3; t++) { acc[r][t][0] = 0.f; acc[r][t][1] = 0.f; }

        for (int d0 = 0; d0 < HD; d0 += 4) {
            float4 q4[6];
            #pragma unroll
            for (int r = 0; r < 6; r++)
                q4[r] = *(const float4*)(Qs + rows[r] * HD + d0);
            #pragma unroll
            for (int dd = 0; dd < 4; dd++) {
                float2 kt[3];
                #pragma unroll
                for (int t = 0; t < 3; t++)
                    kt[t] = *(const float2*)(KT + (d0 + dd) * KT_STRIDE + j0v[t]);
                #pragma unroll
                for (int r = 0; r < 6; r++) {
                    const float q = (dd == 0) ? q4[r].x : (dd == 1) ? q4[r].y
                                  : (dd == 2) ? q4[r].z : q4[r].w;
                    #pragma unroll
                    for (int t = 0; t < 3; t++) {
                        acc[r][t][0] += q * kt[t].x;
                        acc[r][t][1] += q * kt[t].y;
                    }
                }
            }
        }

        // ---- mask + softmax (unnormalized p stored; normalize at output) ----
        float inv[6];
        #pragma unroll
        for (int r = 0; r < 6; r++) {
            const int row = rows[r];
            const int fq  = row / 22;
            #pragma unroll
            for (int t = 0; t < 3; t++) {
                const int ja = j0v[t], jb = ja + 1;
                const bool ma = (ja >= SEQ) || (jf0[t] == fq && ja != row);
                const bool mb = (jb >= SEQ) || (jf1[t] == fq && jb != row);
                acc[r][t][0] = ma ? NEGV : acc[r][t][0] * scale;
                acc[r][t][1] = mb ? NEGV : acc[r][t][1] * scale;
            }
            float m = acc[r][0][0];
            #pragma unroll
            for (int t = 0; t < 3; t++) {
                m = fmaxf(m, acc[r][t][0]); m = fmaxf(m, acc[r][t][1]);
            }
            #pragma unroll
            for (int off = 16; off > 0; off >>= 1)
                m = fmaxf(m, __shfl_xor_sync(0xffffffffu, m, off));
            float ssum = 0.f;
            #pragma unroll
            for (int t = 0; t < 3; t++) {
                float e0 = __expf(acc[r][t][0] - m);
                float e1 = __expf(acc[r][t][1] - m);
                acc[r][t][0] = e0; acc[r][t][1] = e1;
                ssum += e0 + e1;
            }
            #pragma unroll
            for (int off = 16; off > 0; off >>= 1)
                ssum += __shfl_xor_sync(0xffffffffu, ssum, off);
            inv[r] = 1.0f / ssum;
            #pragma unroll
            for (int t = 0; t < 3; t++) {
                if (j0v[t] < SEQ) {
                    float2 p2; p2.x = acc[r][t][0]; p2.y = acc[r][t][1];
                    *(float2*)(pb + (w * 6 + r) * SEQ + j0v[t]) = p2;
                }
            }
        }
        __syncwarp();

        // ---- PV: lane owns d = 2*lane, 2*lane+1 ----
        float o[6][2];
        #pragma unroll
        for (int r = 0; r < 6; r++) { o[r][0] = 0.f; o[r][1] = 0.f; }

        for (int j = 0; j < SEQ; j += 4) {
            float2 v[4];
            #pragma unroll
            for (int u = 0; u < 4; u++)
                v[u] = *(const float2*)(Vs + (j + u) * HD + 2 * lane);
            #pragma unroll
            for (int r = 0; r < 6; r++) {
                float4 p4 = *(const float4*)(pb + (w * 6 + r) * SEQ + j);
                o[r][0] += p4.x * v[0].x + p4.y * v[1].x + p4.z * v[2].x + p4.w * v[3].x;
                o[r][1] += p4.x * v[0].y + p4.y * v[1].y + p4.z * v[2].y + p4.w * v[3].y;
            }
        }

        #pragma unroll
        for (int r = 0; r < 6; r++) {
            if (r < nrows) {
                const int row = rbase + r;
                float2 res; res.x = o[r][0] * inv[r]; res.y = o[r][1] * inv[r];
                *(float2*)(out + ((size_t)b * SEQ + row) * DMODEL + h * HD + 2 * lane) = res;
            }
        }
        __syncwarp();   // pb reused next chunk
    }
}

// ---------------------------------------------------------------------------
extern "C" void kernel_launch(void* const* d_in, const int* in_sizes, int n_in,
                              void* d_out, int out_size)
{
    const float* x  = (const float*)d_in[0];
    const float* Wq = (const float*)d_in[1];
    const float* bq = (const float*)d_in[2];
    const float* Wk = (const float*)d_in[3];
    const float* bk = (const float*)d_in[4];
    const float* Wv = (const float*)d_in[5];
    const float* bv = (const float*)d_in[6];
    float* out = (float*)d_out;

    cudaFuncSetAttribute(attn_kernel,
                         cudaFuncAttributeMaxDynamicSharedMemorySize, SMEM2_BYTES);

    qkv_mma_kernel<<<dim3(M_TOTAL / 256, NH, 3), 256>>>(x, Wq, bq, Wk, bk, Wv, bv);
    attn_kernel<<<BATCH * NH, 512, SMEM2_BYTES>>>(out);
}

// round 4
// speedup vs baseline: 2.4139x; 1.7704x over previous
#include <cuda_runtime.h>

#define BATCH   512
#define SEQ     176
#define DIN     128
#define NH      8
#define HD      64
#define DMODEL  512
#define NEGV    (-9e15f)

#define M_TOTAL (BATCH * SEQ)          // 90112

// scratch: [B, H, S, D] each
static __device__ float g_Q[(size_t)BATCH * NH * SEQ * HD];
static __device__ float g_K[(size_t)BATCH * NH * SEQ * HD];
static __device__ float g_V[(size_t)BATCH * NH * SEQ * HD];

__device__ __forceinline__ unsigned f2tf32(float f) {
    unsigned u;
    asm("cvt.rna.tf32.f32 %0, %1;" : "=r"(u) : "f"(f));
    return u;
}
__device__ __forceinline__ float f2tf32f(float f) {
    return __uint_as_float(f2tf32(f));
}

__device__ __forceinline__ void mma_tf32(float c[4], const unsigned a[4], const unsigned b[2]) {
    asm volatile(
        "mma.sync.aligned.m16n8k8.row.col.f32.tf32.tf32.f32 "
        "{%0,%1,%2,%3}, {%4,%5,%6,%7}, {%8,%9}, {%0,%1,%2,%3};"
        : "+f"(c[0]), "+f"(c[1]), "+f"(c[2]), "+f"(c[3])
        : "r"(a[0]), "r"(a[1]), "r"(a[2]), "r"(a[3]), "r"(b[0]), "r"(b[1]));
}

// ---------------------------------------------------------------------------
// Kernel A: QKV projection with tf32 mma.sync m16n8k8. (unchanged from R3)
// ---------------------------------------------------------------------------
#define SX 20
#define SW 72

__global__ void qkv_mma_kernel(const float* __restrict__ x,
                               const float* __restrict__ Wq, const float* __restrict__ bq,
                               const float* __restrict__ Wk, const float* __restrict__ bk,
                               const float* __restrict__ Wv, const float* __restrict__ bv)
{
    __shared__ unsigned xs[256 * SX];
    __shared__ unsigned ws[16 * SW];

    const int z = blockIdx.z;
    const float* W  = (z == 0) ? Wq : (z == 1) ? Wk : Wv;
    const float* bb = (z == 0) ? bq : (z == 1) ? bk : bv;
    float* dst      = (z == 0) ? g_Q : (z == 1) ? g_K : g_V;
    const bool relu = (z == 2);

    const int tid = threadIdx.x;
    const int w    = tid >> 5;
    const int lane = tid & 31;
    const int gid  = lane >> 2;
    const int tig  = lane & 3;

    const int m0 = blockIdx.x * 256;
    const int h  = blockIdx.y;
    const int n0 = h * HD;

    float acc[2][8][4];
    #pragma unroll
    for (int mt = 0; mt < 2; mt++)
        #pragma unroll
        for (int nt = 0; nt < 8; nt++)
            #pragma unroll
            for (int i = 0; i < 4; i++) acc[mt][nt][i] = 0.f;

    const int xrow = tid >> 2;
    const int xc4  = (tid & 3) * 4;
    const int wrow = tid >> 4;
    const int wc4  = (tid & 15) * 4;

    for (int k0 = 0; k0 < DIN; k0 += 16) {
        __syncthreads();
        #pragma unroll
        for (int i = 0; i < 4; i++) {
            const int r = xrow + i * 64;
            float4 v = *(const float4*)(x + (size_t)(m0 + r) * DIN + k0 + xc4);
            unsigned* p = xs + r * SX + xc4;
            p[0] = f2tf32(v.x); p[1] = f2tf32(v.y); p[2] = f2tf32(v.z); p[3] = f2tf32(v.w);
        }
        {
            float4 v = *(const float4*)(W + (size_t)(k0 + wrow) * DMODEL + n0 + wc4);
            unsigned* p = ws + wrow * SW + wc4;
            p[0] = f2tf32(v.x); p[1] = f2tf32(v.y); p[2] = f2tf32(v.z); p[3] = f2tf32(v.w);
        }
        __syncthreads();

        #pragma unroll
        for (int kk = 0; kk < 16; kk += 8) {
            unsigned a[2][4];
            #pragma unroll
            for (int mt = 0; mt < 2; mt++) {
                const int r = w * 32 + mt * 16 + gid;
                a[mt][0] = xs[(r    ) * SX + kk + tig];
                a[mt][1] = xs[(r + 8) * SX + kk + tig];
                a[mt][2] = xs[(r    ) * SX + kk + tig + 4];
                a[mt][3] = xs[(r + 8) * SX + kk + tig + 4];
            }
            unsigned b[8][2];
            #pragma unroll
            for (int nt = 0; nt < 8; nt++) {
                b[nt][0] = ws[(kk + tig    ) * SW + nt * 8 + gid];
                b[nt][1] = ws[(kk + tig + 4) * SW + nt * 8 + gid];
            }
            #pragma unroll
            for (int mt = 0; mt < 2; mt++)
                #pragma unroll
                for (int nt = 0; nt < 8; nt++)
                    mma_tf32(acc[mt][nt], a[mt], b[nt]);
        }
    }

    float2 bias2[8];
    #pragma unroll
    for (int nt = 0; nt < 8; nt++)
        bias2[nt] = *(const float2*)(bb + n0 + nt * 8 + 2 * tig);

    #pragma unroll
    for (int mt = 0; mt < 2; mt++) {
        #pragma unroll
        for (int half = 0; half < 2; half++) {
            const int m = m0 + w * 32 + mt * 16 + gid + half * 8;
            const int bidx = m / SEQ;
            const int s    = m - bidx * SEQ;
            const size_t base = ((size_t)(bidx * NH + h) * SEQ + s) * HD;
            #pragma unroll
            for (int nt = 0; nt < 8; nt++) {
                float2 o;
                o.x = acc[mt][nt][half * 2 + 0] + bias2[nt].x;
                o.y = acc[mt][nt][half * 2 + 1] + bias2[nt].y;
                if (relu) { o.x = fmaxf(o.x, 0.f); o.y = fmaxf(o.y, 0.f); }
                *(float2*)(dst + base + nt * 8 + 2 * tig) = o;
            }
        }
    }
}

// ---------------------------------------------------------------------------
// Kernel B: attention with tf32 mma. Grid: B*NH. Block: 352 threads (11 warps).
// Warp w owns m-tile rows [w*16, w*16+16). QK^T and PV both on tensor pipe.
// ---------------------------------------------------------------------------
#define KTS 184                        // K^T row stride (24 mod 32 -> CF B-frags)
#define VSS 72                         // V row stride   (8 mod 32  -> CF B-frags)
#define PSS 188                        // P row stride   (28 mod 32 -> CF A-frags)
#define SMEMA_FLOATS (64 * KTS + SEQ * VSS + 11 * 16 * PSS)
#define SMEMA_BYTES  (SMEMA_FLOATS * 4)   // 230144 bytes

__global__ void __launch_bounds__(352, 1)
attn_mma_kernel(float* __restrict__ out)
{
    extern __shared__ float sm[];
    float* KT = sm;                    // [64][184]  (tf32-rounded)
    float* Vs = KT + 64 * KTS;         // [176][72]  (tf32-rounded)
    float* P  = Vs + SEQ * VSS;        // [11][16][188]

    const int tid = threadIdx.x;
    const int bh  = blockIdx.x;
    const int b   = bh >> 3;
    const int h   = bh & 7;

    const float* qg = g_Q + (size_t)bh * SEQ * HD;
    const float* kg = g_K + (size_t)bh * SEQ * HD;
    const float* vg = g_V + (size_t)bh * SEQ * HD;

    // stage K^T and V (tf32-rounded)
    for (int i = tid; i < SEQ * HD; i += 352) {
        const int s = i >> 6, d = i & 63;
        KT[d * KTS + s] = f2tf32f(kg[i]);
    }
    for (int i = tid; i < SEQ * 16; i += 352) {
        const int r = i >> 4, c = (i & 15) * 4;
        float4 v = *(const float4*)(vg + r * HD + c);
        float* p = Vs + r * VSS + c;
        p[0] = f2tf32f(v.x); p[1] = f2tf32f(v.y); p[2] = f2tf32f(v.z); p[3] = f2tf32f(v.w);
    }
    __syncthreads();

    const int w    = tid >> 5;
    const int lane = tid & 31;
    const int gid  = lane >> 2;
    const int tig  = lane & 3;
    const int m0   = w * 16;
    const int row0 = m0 + gid;
    const int row1 = row0 + 8;
    const int f0   = row0 / 22;
    const int f1   = row1 / 22;

    // Q fragments straight from global (L2-resident)
    unsigned qa[8][4];
    {
        const float* q0 = qg + (size_t)row0 * HD;
        const float* q1 = qg + (size_t)row1 * HD;
        #pragma unroll
        for (int ks = 0; ks < 8; ks++) {
            qa[ks][0] = f2tf32(__ldg(q0 + ks * 8 + tig));
            qa[ks][1] = f2tf32(__ldg(q1 + ks * 8 + tig));
            qa[ks][2] = f2tf32(__ldg(q0 + ks * 8 + tig + 4));
            qa[ks][3] = f2tf32(__ldg(q1 + ks * 8 + tig + 4));
        }
    }

    // ---- scores: acc[nt] = Q K^T, 16x176 per warp ----
    float acc[22][4];
    #pragma unroll
    for (int nt = 0; nt < 22; nt++)
        #pragma unroll
        for (int i = 0; i < 4; i++) acc[nt][i] = 0.f;

    #pragma unroll
    for (int ks = 0; ks < 8; ks++) {
        const int k = ks * 8;
        #pragma unroll
        for (int nt = 0; nt < 22; nt++) {
            unsigned bfr[2];
            bfr[0] = __float_as_uint(KT[(k + tig    ) * KTS + nt * 8 + gid]);
            bfr[1] = __float_as_uint(KT[(k + tig + 4) * KTS + nt * 8 + gid]);
            mma_tf32(acc[nt], qa[ks], bfr);
        }
    }

    // ---- mask + exp (no max pass: masked -> -9e15 -> exp underflows to 0) ----
    float sum0 = 0.f, sum1 = 0.f;
    #pragma unroll
    for (int nt = 0; nt < 22; nt++) {
        const int ca = nt * 8 + 2 * tig;
        const int cb = ca + 1;
        const int fa = ca / 22;
        const int fb = cb / 22;
        float s0 = (fa == f0 && ca != row0) ? NEGV : acc[nt][0] * 0.125f;
        float s1 = (fb == f0 && cb != row0) ? NEGV : acc[nt][1] * 0.125f;
        float s2 = (fa == f1 && ca != row1) ? NEGV : acc[nt][2] * 0.125f;
        float s3 = (fb == f1 && cb != row1) ? NEGV : acc[nt][3] * 0.125f;
        acc[nt][0] = __expf(s0);
        acc[nt][1] = __expf(s1);
        acc[nt][2] = __expf(s2);
        acc[nt][3] = __expf(s3);
        sum0 += acc[nt][0] + acc[nt][1];
        sum1 += acc[nt][2] + acc[nt][3];
    }
    sum0 += __shfl_xor_sync(0xffffffffu, sum0, 1);
    sum0 += __shfl_xor_sync(0xffffffffu, sum0, 2);
    sum1 += __shfl_xor_sync(0xffffffffu, sum1, 1);
    sum1 += __shfl_xor_sync(0xffffffffu, sum1, 2);
    const float inv0 = 1.0f / sum0;
    const float inv1 = 1.0f / sum1;

    // ---- store P (tf32-rounded, unnormalized) ----
    float* Pw = P + w * 16 * PSS;
    #pragma unroll
    for (int nt = 0; nt < 22; nt++) {
        const int col = nt * 8 + 2 * tig;
        float2 pa; pa.x = f2tf32f(acc[nt][0]); pa.y = f2tf32f(acc[nt][1]);
        float2 pb2; pb2.x = f2tf32f(acc[nt][2]); pb2.y = f2tf32f(acc[nt][3]);
        *(float2*)(Pw + gid * PSS + col)       = pa;
        *(float2*)(Pw + (gid + 8) * PSS + col) = pb2;
    }
    __syncwarp();

    // ---- PV: o[nt] (16x64 per warp), k over 176 keys ----
    float o[8][4];
    #pragma unroll
    for (int nt = 0; nt < 8; nt++)
        #pragma unroll
        for (int i = 0; i < 4; i++) o[nt][i] = 0.f;

    #pragma unroll
    for (int kk = 0; kk < 22; kk++) {
        const int k = kk * 8;
        unsigned a[4];
        a[0] = __float_as_uint(Pw[ gid      * PSS + k + tig]);
        a[1] = __float_as_uint(Pw[(gid + 8) * PSS + k + tig]);
        a[2] = __float_as_uint(Pw[ gid      * PSS + k + tig + 4]);
        a[3] = __float_as_uint(Pw[(gid + 8) * PSS + k + tig + 4]);
        #pragma unroll
        for (int nt = 0; nt < 8; nt++) {
            unsigned bfr[2];
            bfr[0] = __float_as_uint(Vs[(k + tig    ) * VSS + nt * 8 + gid]);
            bfr[1] = __float_as_uint(Vs[(k + tig + 4) * VSS + nt * 8 + gid]);
            mma_tf32(o[nt], a, bfr);
        }
    }

    // ---- normalize + write out [B,S,H*D] ----
    const size_t obase = (size_t)b * SEQ * DMODEL + (size_t)h * HD;
    #pragma unroll
    for (int nt = 0; nt < 8; nt++) {
        const int d = nt * 8 + 2 * tig;
        float2 r0v; r0v.x = o[nt][0] * inv0; r0v.y = o[nt][1] * inv0;
        float2 r1v; r1v.x = o[nt][2] * inv1; r1v.y = o[nt][3] * inv1;
        *(float2*)(out + obase + (size_t)row0 * DMODEL + d) = r0v;
        *(float2*)(out + obase + (size_t)row1 * DMODEL + d) = r1v;
    }
}

// ---------------------------------------------------------------------------
extern "C" void kernel_launch(void* const* d_in, const int* in_sizes, int n_in,
                              void* d_out, int out_size)
{
    const float* x  = (const float*)d_in[0];
    const float* Wq = (const float*)d_in[1];
    const float* bq = (const float*)d_in[2];
    const float* Wk = (const float*)d_in[3];
    const float* bk = (const float*)d_in[4];
    const float* Wv = (const float*)d_in[5];
    const float* bv = (const float*)d_in[6];
    float* out = (float*)d_out;

    cudaFuncSetAttribute(attn_mma_kernel,
                         cudaFuncAttributeMaxDynamicSharedMemorySize, SMEMA_BYTES);

    qkv_mma_kernel<<<dim3(M_TOTAL / 256, NH, 3), 256>>>(x, Wq, bq, Wk, bk, Wv, bv);
    attn_mma_kernel<<<BATCH * NH, 352, SMEMA_BYTES>>>(out);
}

// round 6
// speedup vs baseline: 3.2477x; 1.3454x over previous
#include <cuda_runtime.h>
#include <cuda_fp16.h>

#define BATCH   512
#define SEQ     176
#define DIN     128
#define NH      8
#define HD      64
#define DMODEL  512
#define NEGV    (-9e15f)

#define M_TOTAL (BATCH * SEQ)          // 90112

// scratch: [B, H, S, D] each
static __device__ float g_Q[(size_t)BATCH * NH * SEQ * HD];
static __device__ float g_K[(size_t)BATCH * NH * SEQ * HD];
static __device__ float g_V[(size_t)BATCH * NH * SEQ * HD];

__device__ __forceinline__ unsigned f2tf32(float f) {
    unsigned u;
    asm("cvt.rna.tf32.f32 %0, %1;" : "=r"(u) : "f"(f));
    return u;
}
__device__ __forceinline__ float f2tf32f(float f) {
    return __uint_as_float(f2tf32(f));
}

__device__ __forceinline__ void mma_tf32(float c[4], const unsigned a[4], unsigned b0, unsigned b1) {
    asm volatile(
        "mma.sync.aligned.m16n8k8.row.col.f32.tf32.tf32.f32 "
        "{%0,%1,%2,%3}, {%4,%5,%6,%7}, {%8,%9}, {%0,%1,%2,%3};"
        : "+f"(c[0]), "+f"(c[1]), "+f"(c[2]), "+f"(c[3])
        : "r"(a[0]), "r"(a[1]), "r"(a[2]), "r"(a[3]), "r"(b0), "r"(b1));
}

__device__ __forceinline__ void mma_f16(float c[4],
                                        unsigned a0, unsigned a1, unsigned a2, unsigned a3,
                                        unsigned b0, unsigned b1) {
    asm volatile(
        "mma.sync.aligned.m16n8k16.row.col.f32.f16.f16.f32 "
        "{%0,%1,%2,%3}, {%4,%5,%6,%7}, {%8,%9}, {%0,%1,%2,%3};"
        : "+f"(c[0]), "+f"(c[1]), "+f"(c[2]), "+f"(c[3])
        : "r"(a0), "r"(a1), "r"(a2), "r"(a3), "r"(b0), "r"(b1));
}

// ---------------------------------------------------------------------------
// Kernel A: QKV projection with tf32 mma.sync m16n8k8. (unchanged)
// ---------------------------------------------------------------------------
#define SX 20
#define SW 72

__global__ void qkv_mma_kernel(const float* __restrict__ x,
                               const float* __restrict__ Wq, const float* __restrict__ bq,
                               const float* __restrict__ Wk, const float* __restrict__ bk,
                               const float* __restrict__ Wv, const float* __restrict__ bv)
{
    __shared__ unsigned xs[256 * SX];
    __shared__ unsigned ws[16 * SW];

    const int z = blockIdx.z;
    const float* W  = (z == 0) ? Wq : (z == 1) ? Wk : Wv;
    const float* bb = (z == 0) ? bq : (z == 1) ? bk : bv;
    float* dst      = (z == 0) ? g_Q : (z == 1) ? g_K : g_V;
    const bool relu = (z == 2);

    const int tid = threadIdx.x;
    const int w    = tid >> 5;
    const int lane = tid & 31;
    const int gid  = lane >> 2;
    const int tig  = lane & 3;

    const int m0 = blockIdx.x * 256;
    const int h  = blockIdx.y;
    const int n0 = h * HD;

    float acc[2][8][4];
    #pragma unroll
    for (int mt = 0; mt < 2; mt++)
        #pragma unroll
        for (int nt = 0; nt < 8; nt++)
            #pragma unroll
            for (int i = 0; i < 4; i++) acc[mt][nt][i] = 0.f;

    const int xrow = tid >> 2;
    const int xc4  = (tid & 3) * 4;
    const int wrow = tid >> 4;
    const int wc4  = (tid & 15) * 4;

    for (int k0 = 0; k0 < DIN; k0 += 16) {
        __syncthreads();
        #pragma unroll
        for (int i = 0; i < 4; i++) {
            const int r = xrow + i * 64;
            float4 v = *(const float4*)(x + (size_t)(m0 + r) * DIN + k0 + xc4);
            unsigned* p = xs + r * SX + xc4;
            p[0] = f2tf32(v.x); p[1] = f2tf32(v.y); p[2] = f2tf32(v.z); p[3] = f2tf32(v.w);
        }
        {
            float4 v = *(const float4*)(W + (size_t)(k0 + wrow) * DMODEL + n0 + wc4);
            unsigned* p = ws + wrow * SW + wc4;
            p[0] = f2tf32(v.x); p[1] = f2tf32(v.y); p[2] = f2tf32(v.z); p[3] = f2tf32(v.w);
        }
        __syncthreads();

        #pragma unroll
        for (int kk = 0; kk < 16; kk += 8) {
            unsigned a[2][4];
            #pragma unroll
            for (int mt = 0; mt < 2; mt++) {
                const int r = w * 32 + mt * 16 + gid;
                a[mt][0] = xs[(r    ) * SX + kk + tig];
                a[mt][1] = xs[(r + 8) * SX + kk + tig];
                a[mt][2] = xs[(r    ) * SX + kk + tig + 4];
                a[mt][3] = xs[(r + 8) * SX + kk + tig + 4];
            }
            unsigned b[8][2];
            #pragma unroll
            for (int nt = 0; nt < 8; nt++) {
                b[nt][0] = ws[(kk + tig    ) * SW + nt * 8 + gid];
                b[nt][1] = ws[(kk + tig + 4) * SW + nt * 8 + gid];
            }
            #pragma unroll
            for (int mt = 0; mt < 2; mt++)
                #pragma unroll
                for (int nt = 0; nt < 8; nt++)
                    mma_tf32(acc[mt][nt], a[mt], b[nt][0], b[nt][1]);
        }
    }

    float2 bias2[8];
    #pragma unroll
    for (int nt = 0; nt < 8; nt++)
        bias2[nt] = *(const float2*)(bb + n0 + nt * 8 + 2 * tig);

    #pragma unroll
    for (int mt = 0; mt < 2; mt++) {
        #pragma unroll
        for (int half = 0; half < 2; half++) {
            const int m = m0 + w * 32 + mt * 16 + gid + half * 8;
            const int bidx = m / SEQ;
            const int s    = m - bidx * SEQ;
            const size_t base = ((size_t)(bidx * NH + h) * SEQ + s) * HD;
            #pragma unroll
            for (int nt = 0; nt < 8; nt++) {
                float2 o;
                o.x = acc[mt][nt][half * 2 + 0] + bias2[nt].x;
                o.y = acc[mt][nt][half * 2 + 1] + bias2[nt].y;
                if (relu) { o.x = fmaxf(o.x, 0.f); o.y = fmaxf(o.y, 0.f); }
                *(float2*)(dst + base + nt * 8 + 2 * tig) = o;
            }
        }
    }
}

// ---------------------------------------------------------------------------
// Kernel B: fused chunked attention.
// Grid: B*NH. Block: 352 threads (11 warps), 2 CTAs/SM.
// Warp w owns rows [w*16, w*16+16). For each 16-key chunk:
//   16 tf32 score mmas -> mask+exp -> pack half2 (direct A-frag) -> 8 fp16 PV mmas.
// KT2: [32 rows][180 float2]: row (ks*4+tig) holds, for each key s, the
//      float2 (K[s][ks*8+tig], K[s][ks*8+tig+4]).  (FIXED: row = 176+pad float2)
// Vp2: [44 rows][76 uint2]:  row (c*4+tig) packs keys {16c+2tig,+1} and
//      {16c+2tig+8,+9} as 2x half2, per dim d.
// ---------------------------------------------------------------------------
#define KT2S 180                    // float2 stride (360 words; tig-stride 8 mod 32 -> CF)
#define VP2S 76                     // uint2 stride  (152 words, 24 mod 32 -> CF LDS.64)
#define KT2_BYTES (32 * KT2S * 8)   // 46080
#define VP2_BYTES (44 * VP2S * 8)   // 26752
#define SMEMA_BYTES (KT2_BYTES + VP2_BYTES)   // 72832

__global__ void __launch_bounds__(352, 2)
attn_mma_kernel(float* __restrict__ out)
{
    extern __shared__ char smraw[];
    float*    KT2w = (float*)smraw;                       // word view for staging
    float2*   KT2  = (float2*)smraw;
    uint2*    Vp2  = (uint2*)(smraw + KT2_BYTES);

    const int tid = threadIdx.x;
    const int bh  = blockIdx.x;
    const int b   = bh >> 3;
    const int h   = bh & 7;

    const float* qg = g_Q + (size_t)bh * SEQ * HD;
    const float* kg = g_K + (size_t)bh * SEQ * HD;
    const float* vg = g_V + (size_t)bh * SEQ * HD;

    // ---- stage K^T (pair-packed, tf32-rounded); coalesced reads, scatter writes ----
    for (int i = tid; i < SEQ * HD; i += 352) {
        const int s = i >> 6, d = i & 63;
        const int ks = d >> 3, t = d & 7;
        const int tig_ = t & 3, slot = t >> 2;
        KT2w[((ks * 4 + tig_) * KT2S + s) * 2 + slot] = f2tf32f(kg[i]);
    }
    // ---- stage V (4-key packed half2x2); coalesced reads ----
    for (int i = tid; i < 44 * HD; i += 352) {
        const int r = i >> 6, d = i & 63;       // r = c*4 + tg
        const int c = r >> 2, tg = r & 3;
        const int k0 = 16 * c + 2 * tg;         // keys k0, k0+1, k0+8, k0+9
        __half2 lo = __floats2half2_rn(vg[(k0    ) * HD + d], vg[(k0 + 1) * HD + d]);
        __half2 hi = __floats2half2_rn(vg[(k0 + 8) * HD + d], vg[(k0 + 9) * HD + d]);
        uint2 pk;
        pk.x = *reinterpret_cast<unsigned*>(&lo);
        pk.y = *reinterpret_cast<unsigned*>(&hi);
        Vp2[r * VP2S + d] = pk;
    }
    __syncthreads();

    const int w    = tid >> 5;
    const int lane = tid & 31;
    const int gid  = lane >> 2;
    const int tig  = lane & 3;
    const int row0 = w * 16 + gid;
    const int row1 = row0 + 8;
    const int f0   = row0 / 22;
    const int f1   = row1 / 22;

    // ---- Q fragments from global (L2-resident) ----
    unsigned qa[8][4];
    {
        const float* q0 = qg + (size_t)row0 * HD;
        const float* q1 = qg + (size_t)row1 * HD;
        #pragma unroll
        for (int ks = 0; ks < 8; ks++) {
            qa[ks][0] = f2tf32(__ldg(q0 + ks * 8 + tig));
            qa[ks][1] = f2tf32(__ldg(q1 + ks * 8 + tig));
            qa[ks][2] = f2tf32(__ldg(q0 + ks * 8 + tig + 4));
            qa[ks][3] = f2tf32(__ldg(q1 + ks * 8 + tig + 4));
        }
    }

    float o[8][4];
    #pragma unroll
    for (int nt = 0; nt < 8; nt++)
        #pragma unroll
        for (int i = 0; i < 4; i++) o[nt][i] = 0.f;

    float sum0 = 0.f, sum1 = 0.f;

    #pragma unroll
    for (int c = 0; c < 11; c++) {
        // ---- scores for 16-key chunk (cols 16c .. 16c+15) ----
        float s0[4] = {0.f, 0.f, 0.f, 0.f};
        float s1[4] = {0.f, 0.f, 0.f, 0.f};
        #pragma unroll
        for (int ks = 0; ks < 8; ks++) {
            const float2* krow = KT2 + (ks * 4 + tig) * KT2S + 16 * c + gid;
            float2 b0 = krow[0];      // cols 16c+gid      (n-tile 2c)
            float2 b1 = krow[8];      // cols 16c+8+gid    (n-tile 2c+1)
            mma_tf32(s0, qa[ks], __float_as_uint(b0.x), __float_as_uint(b0.y));
            mma_tf32(s1, qa[ks], __float_as_uint(b1.x), __float_as_uint(b1.y));
        }

        // ---- mask + exp (no max pass; masked -> exp underflows to 0) ----
        const int ca = 16 * c + 2 * tig;    // s0 cols: ca, ca+1 ; s1 cols: ca+8, ca+9
        const int cb = ca + 1;
        const int cc = ca + 8;
        const int cd = ca + 9;
        const int fa = ca / 22, fb = cb / 22, fc = cc / 22, fd = cd / 22;

        float e00 = __expf((fa == f0 && ca != row0) ? NEGV : s0[0] * 0.125f);
        float e01 = __expf((fb == f0 && cb != row0) ? NEGV : s0[1] * 0.125f);
        float e02 = __expf((fa == f1 && ca != row1) ? NEGV : s0[2] * 0.125f);
        float e03 = __expf((fb == f1 && cb != row1) ? NEGV : s0[3] * 0.125f);
        float e10 = __expf((fc == f0 && cc != row0) ? NEGV : s1[0] * 0.125f);
        float e11 = __expf((fd == f0 && cd != row0) ? NEGV : s1[1] * 0.125f);
        float e12 = __expf((fc == f1 && cc != row1) ? NEGV : s1[2] * 0.125f);
        float e13 = __expf((fd == f1 && cd != row1) ? NEGV : s1[3] * 0.125f);

        sum0 += (e00 + e01) + (e10 + e11);
        sum1 += (e02 + e03) + (e12 + e13);

        // ---- pack to fp16 A-fragments (layout identity, no shuffles) ----
        __half2 h0 = __floats2half2_rn(e00, e01);   // A[row0][k=2tig,2tig+1]
        __half2 h1 = __floats2half2_rn(e02, e03);   // A[row1][k=2tig,2tig+1]
        __half2 h2 = __floats2half2_rn(e10, e11);   // A[row0][k=2tig+8,+9]
        __half2 h3 = __floats2half2_rn(e12, e13);   // A[row1][k=2tig+8,+9]
        unsigned a0 = *reinterpret_cast<unsigned*>(&h0);
        unsigned a1 = *reinterpret_cast<unsigned*>(&h1);
        unsigned a2 = *reinterpret_cast<unsigned*>(&h2);
        unsigned a3 = *reinterpret_cast<unsigned*>(&h3);

        // ---- PV partial for this chunk: 8 fp16 mmas ----
        const uint2* vrow = Vp2 + (c * 4 + tig) * VP2S + gid;
        #pragma unroll
        for (int nt = 0; nt < 8; nt++) {
            uint2 bf = vrow[nt * 8];
            mma_f16(o[nt], a0, a1, a2, a3, bf.x, bf.y);
        }
    }

    // ---- row sums across the 4 tig lanes of each quad ----
    sum0 += __shfl_xor_sync(0xffffffffu, sum0, 1);
    sum0 += __shfl_xor_sync(0xffffffffu, sum0, 2);
    sum1 += __shfl_xor_sync(0xffffffffu, sum1, 1);
    sum1 += __shfl_xor_sync(0xffffffffu, sum1, 2);
    const float inv0 = 1.0f / sum0;
    const float inv1 = 1.0f / sum1;

    // ---- normalize + write out [B,S,H*D] ----
    const size_t obase = (size_t)b * SEQ * DMODEL + (size_t)h * HD;
    #pragma unroll
    for (int nt = 0; nt < 8; nt++) {
        const int d = nt * 8 + 2 * tig;
        float2 r0v; r0v.x = o[nt][0] * inv0; r0v.y = o[nt][1] * inv0;
        float2 r1v; r1v.x = o[nt][2] * inv1; r1v.y = o[nt][3] * inv1;
        *(float2*)(out + obase + (size_t)row0 * DMODEL + d) = r0v;
        *(float2*)(out + obase + (size_t)row1 * DMODEL + d) = r1v;
    }
}

// ---------------------------------------------------------------------------
extern "C" void kernel_launch(void* const* d_in, const int* in_sizes, int n_in,
                              void* d_out, int out_size)
{
    const float* x  = (const float*)d_in[0];
    const float* Wq = (const float*)d_in[1];
    const float* bq = (const float*)d_in[2];
    const float* Wk = (const float*)d_in[3];
    const float* bk = (const float*)d_in[4];
    const float* Wv = (const float*)d_in[5];
    const float* bv = (const float*)d_in[6];
    float* out = (float*)d_out;

    cudaFuncSetAttribute(attn_mma_kernel,
                         cudaFuncAttributeMaxDynamicSharedMemorySize, SMEMA_BYTES);

    qkv_mma_kernel<<<dim3(M_TOTAL / 256, NH, 3), 256>>>(x, Wq, bq, Wk, bk, Wv, bv);
    attn_mma_kernel<<<BATCH * NH, 352, SMEMA_BYTES>>>(out);
}

// round 7
// speedup vs baseline: 3.6922x; 1.1369x over previous
#include <cuda_runtime.h>
#include <cuda_fp16.h>

#define BATCH   512
#define SEQ     176
#define DIN     128
#define NH      8
#define HD      64
#define DMODEL  512
#define NEGV    (-9e15f)

#define M_TOTAL (BATCH * SEQ)          // 90112

// scratch: [B, H, S, D] each
static __device__ float g_Q[(size_t)BATCH * NH * SEQ * HD];
static __device__ float g_K[(size_t)BATCH * NH * SEQ * HD];
static __device__ float g_V[(size_t)BATCH * NH * SEQ * HD];

__device__ __forceinline__ unsigned packh2(__half2 h) {
    return *reinterpret_cast<unsigned*>(&h);
}

__device__ __forceinline__ void mma_f16(float c[4],
                                        unsigned a0, unsigned a1, unsigned a2, unsigned a3,
                                        unsigned b0, unsigned b1) {
    asm volatile(
        "mma.sync.aligned.m16n8k16.row.col.f32.f16.f16.f32 "
        "{%0,%1,%2,%3}, {%4,%5,%6,%7}, {%8,%9}, {%0,%1,%2,%3};"
        : "+f"(c[0]), "+f"(c[1]), "+f"(c[2]), "+f"(c[3])
        : "r"(a0), "r"(a1), "r"(a2), "r"(a3), "r"(b0), "r"(b1));
}

// ---------------------------------------------------------------------------
// Kernel A: QKV projection, fp16 mma m16n8k16.
// Grid: (M_TOTAL/256, NH, 3). Block: 256 threads (8 warps).
// Warp w: rows [w*32, w*32+32) = 2 m16 tiles x 8 n8 tiles; one k16 step per k0.
// xs_u[r][p] = half2(x[r][k0+2p], x[r][k0+2p+1]), stride 12 (CF a-frag loads).
// ws_u[n][p] = half2(W[k0+2p][n0+n], W[k0+2p+1][n0+n]), stride 12 (CF b-frags).
// ---------------------------------------------------------------------------
#define XSU 12
#define WSU 12

__global__ void __launch_bounds__(256, 2)
qkv_mma_kernel(const float* __restrict__ x,
               const float* __restrict__ Wq, const float* __restrict__ bq,
               const float* __restrict__ Wk, const float* __restrict__ bk,
               const float* __restrict__ Wv, const float* __restrict__ bv)
{
    __shared__ unsigned xs_u[256 * XSU];
    __shared__ unsigned ws_u[64 * WSU];

    const int z = blockIdx.z;
    const float* W  = (z == 0) ? Wq : (z == 1) ? Wk : Wv;
    const float* bb = (z == 0) ? bq : (z == 1) ? bk : bv;
    float* dst      = (z == 0) ? g_Q : (z == 1) ? g_K : g_V;
    const bool relu = (z == 2);

    const int tid  = threadIdx.x;
    const int w    = tid >> 5;
    const int lane = tid & 31;
    const int gid  = lane >> 2;
    const int tig  = lane & 3;

    const int m0 = blockIdx.x * 256;
    const int h  = blockIdx.y;
    const int n0 = h * HD;

    float acc[2][8][4];
    #pragma unroll
    for (int mt = 0; mt < 2; mt++)
        #pragma unroll
        for (int nt = 0; nt < 8; nt++)
            #pragma unroll
            for (int i = 0; i < 4; i++) acc[mt][nt][i] = 0.f;

    const int xr = tid >> 2;          // 0..63 (+64j)
    const int xf = tid & 3;           // float4 index 0..3

    for (int k0 = 0; k0 < DIN; k0 += 16) {
        __syncthreads();
        // stage x: 256 rows x 16 k (as 8 half2 pairs per row)
        #pragma unroll
        for (int j = 0; j < 4; j++) {
            const int r = xr + j * 64;
            float4 v = *(const float4*)(x + (size_t)(m0 + r) * DIN + k0 + xf * 4);
            unsigned* pp = xs_u + r * XSU + xf * 2;
            pp[0] = packh2(__floats2half2_rn(v.x, v.y));
            pp[1] = packh2(__floats2half2_rn(v.z, v.w));
        }
        // stage W^T: 64 cols x 8 k-pairs
        #pragma unroll
        for (int j = 0; j < 2; j++) {
            const int idx = tid + j * 256;          // 0..511
            const int p = idx >> 6, n = idx & 63;
            const float w0 = W[(size_t)(k0 + 2 * p    ) * DMODEL + n0 + n];
            const float w1 = W[(size_t)(k0 + 2 * p + 1) * DMODEL + n0 + n];
            ws_u[n * WSU + p] = packh2(__floats2half2_rn(w0, w1));
        }
        __syncthreads();

        // one k16 mma step
        unsigned a[2][4];
        #pragma unroll
        for (int mt = 0; mt < 2; mt++) {
            const int r0 = w * 32 + mt * 16 + gid;
            a[mt][0] = xs_u[(r0    ) * XSU + tig];
            a[mt][1] = xs_u[(r0 + 8) * XSU + tig];
            a[mt][2] = xs_u[(r0    ) * XSU + tig + 4];
            a[mt][3] = xs_u[(r0 + 8) * XSU + tig + 4];
        }
        #pragma unroll
        for (int nt = 0; nt < 8; nt++) {
            const unsigned b0 = ws_u[(nt * 8 + gid) * WSU + tig];
            const unsigned b1 = ws_u[(nt * 8 + gid) * WSU + tig + 4];
            mma_f16(acc[0][nt], a[0][0], a[0][1], a[0][2], a[0][3], b0, b1);
            mma_f16(acc[1][nt], a[1][0], a[1][1], a[1][2], a[1][3], b0, b1);
        }
    }

    // epilogue: bias (+ReLU for V), write [B,H,S,D]
    float2 bias2[8];
    #pragma unroll
    for (int nt = 0; nt < 8; nt++)
        bias2[nt] = *(const float2*)(bb + n0 + nt * 8 + 2 * tig);

    #pragma unroll
    for (int mt = 0; mt < 2; mt++) {
        #pragma unroll
        for (int half = 0; half < 2; half++) {
            const int m = m0 + w * 32 + mt * 16 + gid + half * 8;
            const int bidx = m / SEQ;
            const int s    = m - bidx * SEQ;
            const size_t base = ((size_t)(bidx * NH + h) * SEQ + s) * HD;
            #pragma unroll
            for (int nt = 0; nt < 8; nt++) {
                float2 o;
                o.x = acc[mt][nt][half * 2 + 0] + bias2[nt].x;
                o.y = acc[mt][nt][half * 2 + 1] + bias2[nt].y;
                if (relu) { o.x = fmaxf(o.x, 0.f); o.y = fmaxf(o.y, 0.f); }
                *(float2*)(dst + base + nt * 8 + 2 * tig) = o;
            }
        }
    }
}

// ---------------------------------------------------------------------------
// Kernel B: fused chunked attention, all-fp16 mma.
// Grid: B*NH. Block: 352 threads (11 warps), 2 CTAs/SM.
// Warp w owns rows [w*16, w*16+16). Per 16-key chunk:
//   8 fp16 score mmas -> mask+exp -> pack half2 (direct A-frag) -> 8 fp16 PV mmas.
// KTh: [16 rows][180 uint2]: row (ks*4+tg) at key s = uint2{
//        half2(K[s][16ks+2tg], +1), half2(K[s][16ks+2tg+8], +9) }.
// Vp2: [44 rows][76 uint2]: row (c*4+tg) packs keys {16c+2tg,+1} and
//        {16c+2tg+8,+9} as 2x half2, per dim d.
// ---------------------------------------------------------------------------
#define KTHS 180                     // uint2 stride (360 words; CF both phases)
#define VP2S 76                      // uint2 stride (152 words; CF)
#define KTH_BYTES (16 * KTHS * 8)    // 23040
#define VP2_BYTES (44 * VP2S * 8)    // 26752
#define SMEMA_BYTES (KTH_BYTES + VP2_BYTES)   // 49792

__global__ void __launch_bounds__(352, 2)
attn_mma_kernel(float* __restrict__ out)
{
    extern __shared__ char smraw[];
    uint2*    KTh  = (uint2*)smraw;
    unsigned* KThw = (unsigned*)smraw;                 // 32-bit view for staging
    uint2*    Vp2  = (uint2*)(smraw + KTH_BYTES);

    const int tid = threadIdx.x;
    const int bh  = blockIdx.x;
    const int b   = bh >> 3;
    const int h   = bh & 7;

    const float* qg = g_Q + (size_t)bh * SEQ * HD;
    const float* kg = g_K + (size_t)bh * SEQ * HD;
    const float* vg = g_V + (size_t)bh * SEQ * HD;

    // ---- stage K^T (half2 k-pair packed); coalesced float2 reads ----
    for (int i = tid; i < SEQ * 32; i += 352) {
        const int s = i >> 5, p = i & 31;              // p = d/2
        float2 kv = *(const float2*)(kg + s * HD + 2 * p);
        const int ks = p >> 3, dd2 = p & 7;
        const int tg = dd2 & 3, slot = dd2 >> 2;
        KThw[((ks * 4 + tg) * KTHS + s) * 2 + slot] =
            packh2(__floats2half2_rn(kv.x, kv.y));
    }
    // ---- stage V (4-key packed half2x2); coalesced reads ----
    for (int i = tid; i < 44 * HD; i += 352) {
        const int r = i >> 6, d = i & 63;              // r = c*4 + tg
        const int c = r >> 2, tg = r & 3;
        const int k0 = 16 * c + 2 * tg;                // keys k0, k0+1, k0+8, k0+9
        uint2 pk;
        pk.x = packh2(__floats2half2_rn(vg[(k0    ) * HD + d], vg[(k0 + 1) * HD + d]));
        pk.y = packh2(__floats2half2_rn(vg[(k0 + 8) * HD + d], vg[(k0 + 9) * HD + d]));
        Vp2[r * VP2S + d] = pk;
    }
    __syncthreads();

    const int w    = tid >> 5;
    const int lane = tid & 31;
    const int gid  = lane >> 2;
    const int tig  = lane & 3;
    const int row0 = w * 16 + gid;
    const int row1 = row0 + 8;
    const int f0   = row0 / 22;
    const int f1   = row1 / 22;

    // ---- Q fragments (fp16) from global (L2-resident) ----
    unsigned qa[4][4];
    {
        const float* q0 = qg + (size_t)row0 * HD;
        const float* q1 = qg + (size_t)row1 * HD;
        #pragma unroll
        for (int ks = 0; ks < 4; ks++) {
            float2 v0 = *(const float2*)(q0 + 16 * ks + 2 * tig);
            float2 v1 = *(const float2*)(q0 + 16 * ks + 2 * tig + 8);
            float2 v2 = *(const float2*)(q1 + 16 * ks + 2 * tig);
            float2 v3 = *(const float2*)(q1 + 16 * ks + 2 * tig + 8);
            qa[ks][0] = packh2(__floats2half2_rn(v0.x, v0.y));  // row0, k 2tig..+1
            qa[ks][1] = packh2(__floats2half2_rn(v2.x, v2.y));  // row1, k 2tig..+1
            qa[ks][2] = packh2(__floats2half2_rn(v1.x, v1.y));  // row0, k 2tig+8..+9
            qa[ks][3] = packh2(__floats2half2_rn(v3.x, v3.y));  // row1, k 2tig+8..+9
        }
    }

    float o[8][4];
    #pragma unroll
    for (int nt = 0; nt < 8; nt++)
        #pragma unroll
        for (int i = 0; i < 4; i++) o[nt][i] = 0.f;

    float sum0 = 0.f, sum1 = 0.f;

    #pragma unroll
    for (int c = 0; c < 11; c++) {
        // ---- scores for 16-key chunk (cols 16c .. 16c+15): 8 fp16 mmas ----
        float s0[4] = {0.f, 0.f, 0.f, 0.f};
        float s1[4] = {0.f, 0.f, 0.f, 0.f};
        #pragma unroll
        for (int ks = 0; ks < 4; ks++) {
            const uint2* kr = KTh + (ks * 4 + tig) * KTHS + 16 * c + gid;
            uint2 kb0 = kr[0];      // keys 16c+gid     (n-tile 2c)
            uint2 kb1 = kr[8];      // keys 16c+8+gid   (n-tile 2c+1)
            mma_f16(s0, qa[ks][0], qa[ks][1], qa[ks][2], qa[ks][3], kb0.x, kb0.y);
            mma_f16(s1, qa[ks][0], qa[ks][1], qa[ks][2], qa[ks][3], kb1.x, kb1.y);
        }

        // ---- mask + exp (no max pass; masked -> exp underflows to 0) ----
        const int ca = 16 * c + 2 * tig;    // s0 cols: ca, ca+1 ; s1 cols: ca+8, ca+9
        const int cb = ca + 1;
        const int cc = ca + 8;
        const int cd = ca + 9;
        const int fa = ca / 22, fb = cb / 22, fc = cc / 22, fd = cd / 22;

        float e00 = __expf((fa == f0 && ca != row0) ? NEGV : s0[0] * 0.125f);
        float e01 = __expf((fb == f0 && cb != row0) ? NEGV : s0[1] * 0.125f);
        float e02 = __expf((fa == f1 && ca != row1) ? NEGV : s0[2] * 0.125f);
        float e03 = __expf((fb == f1 && cb != row1) ? NEGV : s0[3] * 0.125f);
        float e10 = __expf((fc == f0 && cc != row0) ? NEGV : s1[0] * 0.125f);
        float e11 = __expf((fd == f0 && cd != row0) ? NEGV : s1[1] * 0.125f);
        float e12 = __expf((fc == f1 && cc != row1) ? NEGV : s1[2] * 0.125f);
        float e13 = __expf((fd == f1 && cd != row1) ? NEGV : s1[3] * 0.125f);

        sum0 += (e00 + e01) + (e10 + e11);
        sum1 += (e02 + e03) + (e12 + e13);

        // ---- pack to fp16 A-fragments (layout identity, no shuffles) ----
        unsigned a0 = packh2(__floats2half2_rn(e00, e01));   // row0, k 2tig..+1
        unsigned a1 = packh2(__floats2half2_rn(e02, e03));   // row1, k 2tig..+1
        unsigned a2 = packh2(__floats2half2_rn(e10, e11));   // row0, k 2tig+8..+9
        unsigned a3 = packh2(__floats2half2_rn(e12, e13));   // row1, k 2tig+8..+9

        // ---- PV partial for this chunk: 8 fp16 mmas ----
        const uint2* vrow = Vp2 + (c * 4 + tig) * VP2S + gid;
        #pragma unroll
        for (int nt = 0; nt < 8; nt++) {
            uint2 bf = vrow[nt * 8];
            mma_f16(o[nt], a0, a1, a2, a3, bf.x, bf.y);
        }
    }

    // ---- row sums across the 4 tig lanes of each quad ----
    sum0 += __shfl_xor_sync(0xffffffffu, sum0, 1);
    sum0 += __shfl_xor_sync(0xffffffffu, sum0, 2);
    sum1 += __shfl_xor_sync(0xffffffffu, sum1, 1);
    sum1 += __shfl_xor_sync(0xffffffffu, sum1, 2);
    const float inv0 = 1.0f / sum0;
    const float inv1 = 1.0f / sum1;

    // ---- normalize + write out [B,S,H*D] ----
    const size_t obase = (size_t)b * SEQ * DMODEL + (size_t)h * HD;
    #pragma unroll
    for (int nt = 0; nt < 8; nt++) {
        const int d = nt * 8 + 2 * tig;
        float2 r0v; r0v.x = o[nt][0] * inv0; r0v.y = o[nt][1] * inv0;
        float2 r1v; r1v.x = o[nt][2] * inv1; r1v.y = o[nt][3] * inv1;
        *(float2*)(out + obase + (size_t)row0 * DMODEL + d) = r0v;
        *(float2*)(out + obase + (size_t)row1 * DMODEL + d) = r1v;
    }
}

// ---------------------------------------------------------------------------
extern "C" void kernel_launch(void* const* d_in, const int* in_sizes, int n_in,
                              void* d_out, int out_size)
{
    const float* x  = (const float*)d_in[0];
    const float* Wq = (const float*)d_in[1];
    const float* bq = (const float*)d_in[2];
    const float* Wk = (const float*)d_in[3];
    const float* bk = (const float*)d_in[4];
    const float* Wv = (const float*)d_in[5];
    const float* bv = (const float*)d_in[6];
    float* out = (float*)d_out;

    cudaFuncSetAttribute(attn_mma_kernel,
                         cudaFuncAttributeMaxDynamicSharedMemorySize, SMEMA_BYTES);

    qkv_mma_kernel<<<dim3(M_TOTAL / 256, NH, 3), 256>>>(x, Wq, bq, Wk, bk, Wv, bv);
    attn_mma_kernel<<<BATCH * NH, 352, SMEMA_BYTES>>>(out);
}

// round 8
// speedup vs baseline: 6.9660x; 1.8867x over previous
#include <cuda_runtime.h>
#include <cuda_fp16.h>

#define BATCH   512
#define SEQ     176
#define DIN     128
#define NH      8
#define HD      64
#define DMODEL  512
#define NEGV    (-9e15f)

// ---------------- smem layout (bytes) ----------------
#define WBUF_STRIDE 68                            // uint per n-row (CF b-frags)
#define WBUF_BYTES  (64 * WBUF_STRIDE * 4)        // 17408
#define KTHS        180                           // uint2 stride (CF score b-frags)
#define KTH_BYTES   (16 * KTHS * 8)               // 23040
#define VSP_STRIDE  33                            // uint per key row
#define VSP_BYTES   (SEQ * VSP_STRIDE * 4)        // 23232
#define XS_STRIDE   68                            // uint per x row (CF a-frags)
#define XS_BYTES    (SEQ * XS_STRIDE * 4)         // 47872
#define VP2S        76                            // uint2 stride (CF PV b-frags)
#define VP2_BYTES   (44 * VP2S * 8)               // 26752 (overlays xs)

#define OFF_WBUF 0
#define OFF_KTH  (OFF_WBUF + WBUF_BYTES)
#define OFF_VSP  (OFF_KTH + KTH_BYTES)
#define OFF_XS   (OFF_VSP + VSP_BYTES)
#define OFF_VP2  OFF_XS
#define SMEM_TOTAL (OFF_XS + XS_BYTES)            // 111552

__device__ __forceinline__ unsigned packh2(__half2 h) {
    return *reinterpret_cast<unsigned*>(&h);
}
__device__ __forceinline__ __half geth(unsigned w, int sel) {
    __half2 h = *reinterpret_cast<__half2*>(&w);
    return sel ? __high2half(h) : __low2half(h);
}

__device__ __forceinline__ void mma_f16(float c[4],
                                        unsigned a0, unsigned a1, unsigned a2, unsigned a3,
                                        unsigned b0, unsigned b1) {
    asm volatile(
        "mma.sync.aligned.m16n8k16.row.col.f32.f16.f16.f32 "
        "{%0,%1,%2,%3}, {%4,%5,%6,%7}, {%8,%9}, {%0,%1,%2,%3};"
        : "+f"(c[0]), "+f"(c[1]), "+f"(c[2]), "+f"(c[3])
        : "r"(a0), "r"(a1), "r"(a2), "r"(a3), "r"(b0), "r"(b1));
}

// ---------------------------------------------------------------------------
// Fully fused kernel: one block per (b,h). 352 threads (11 warps), 2 CTAs/SM.
// Phase 1: QKV projections via fp16 mma (3 passes over matrices, x staged once).
//   - V C-frags -> Vsp (plain half2 words) with bias+ReLU
//   - K C-frags -> KTh DIRECTLY (C-frag word == score-B-operand word)
//   - Q C-frags -> qa registers DIRECTLY (C-frag == score-A-fragment), x0.125
// Repack: Vsp -> Vp2 (PV B-operand layout), overlaying dead x region.
// Phase 2: per-16-key-chunk: 8 score mmas -> mask+exp -> pack -> 8 PV mmas.
// ---------------------------------------------------------------------------
__global__ void __launch_bounds__(352, 2)
fused_attn_kernel(const float* __restrict__ x,
                  const float* __restrict__ Wq, const float* __restrict__ bq,
                  const float* __restrict__ Wk, const float* __restrict__ bk,
                  const float* __restrict__ Wv, const float* __restrict__ bv,
                  float* __restrict__ out)
{
    extern __shared__ char sm[];
    unsigned* Wbuf = (unsigned*)(sm + OFF_WBUF);   // [64 n][68] half2 k-pairs
    uint2*    KTh  = (uint2*)(sm + OFF_KTH);       // [16][180] score B operand
    unsigned* KThw = (unsigned*)(sm + OFF_KTH);
    unsigned* Vsp  = (unsigned*)(sm + OFF_VSP);    // [176][33] plain half2 words
    unsigned* xs   = (unsigned*)(sm + OFF_XS);     // [176][68] half2 k-pairs
    uint2*    Vp2  = (uint2*)(sm + OFF_VP2);       // [44][76] PV B operand

    const int tid = threadIdx.x;
    const int bh  = blockIdx.x;
    const int b   = bh >> 3;
    const int h   = bh & 7;
    const int n0  = h * HD;

    // ---- stage x[b] once as fp16 k-pairs ----
    const float* xb = x + (size_t)b * SEQ * DIN;
    for (int i = tid; i < SEQ * 64; i += 352) {
        const int r = i >> 6, p = i & 63;
        float2 v = *(const float2*)(xb + r * DIN + 2 * p);
        xs[r * XS_STRIDE + p] = packh2(__floats2half2_rn(v.x, v.y));
    }

    const int w    = tid >> 5;
    const int lane = tid & 31;
    const int gid  = lane >> 2;
    const int tig  = lane & 3;
    const int row0 = w * 16 + gid;
    const int row1 = row0 + 8;

    unsigned qa[4][4];   // Q A-fragments, produced by z==2 pass

    // ---- Phase 1: three projection passes (V, K, Q) ----
    #pragma unroll 1
    for (int z = 0; z < 3; z++) {
        const float* W  = (z == 0) ? Wv : (z == 1) ? Wk : Wq;
        const float* bb = (z == 0) ? bv : (z == 1) ? bk : bq;

        __syncthreads();   // Wbuf reuse / xs ready on first iter
        for (int i = tid; i < 64 * 64; i += 352) {
            const int n = i & 63, p = i >> 6;
            const float w0 = W[(size_t)(2 * p    ) * DMODEL + n0 + n];
            const float w1 = W[(size_t)(2 * p + 1) * DMODEL + n0 + n];
            Wbuf[n * WBUF_STRIDE + p] = packh2(__floats2half2_rn(w0, w1));
        }
        __syncthreads();

        float acc[8][4];
        #pragma unroll
        for (int nt = 0; nt < 8; nt++)
            #pragma unroll
            for (int i = 0; i < 4; i++) acc[nt][i] = 0.f;

        #pragma unroll
        for (int ks = 0; ks < 8; ks++) {
            const unsigned a0 = xs[row0 * XS_STRIDE + 8 * ks + tig];
            const unsigned a1 = xs[row1 * XS_STRIDE + 8 * ks + tig];
            const unsigned a2 = xs[row0 * XS_STRIDE + 8 * ks + tig + 4];
            const unsigned a3 = xs[row1 * XS_STRIDE + 8 * ks + tig + 4];
            #pragma unroll
            for (int nt = 0; nt < 8; nt++) {
                const unsigned b0 = Wbuf[(nt * 8 + gid) * WBUF_STRIDE + 8 * ks + tig];
                const unsigned b1 = Wbuf[(nt * 8 + gid) * WBUF_STRIDE + 8 * ks + tig + 4];
                mma_f16(acc[nt], a0, a1, a2, a3, b0, b1);
            }
        }

        if (z == 0) {
            // V: bias + ReLU -> Vsp plain layout
            #pragma unroll
            for (int nt = 0; nt < 8; nt++) {
                float2 bias = *(const float2*)(bb + n0 + nt * 8 + 2 * tig);
                float c0 = fmaxf(acc[nt][0] + bias.x, 0.f);
                float c1 = fmaxf(acc[nt][1] + bias.y, 0.f);
                float c2 = fmaxf(acc[nt][2] + bias.x, 0.f);
                float c3 = fmaxf(acc[nt][3] + bias.y, 0.f);
                Vsp[row0 * VSP_STRIDE + nt * 4 + tig] = packh2(__floats2half2_rn(c0, c1));
                Vsp[row1 * VSP_STRIDE + nt * 4 + tig] = packh2(__floats2half2_rn(c2, c3));
            }
        } else if (z == 1) {
            // K: bias -> KTh DIRECT (C-frag word == B-operand word)
            #pragma unroll
            for (int nt = 0; nt < 8; nt++) {
                float2 bias = *(const float2*)(bb + n0 + nt * 8 + 2 * tig);
                float c0 = acc[nt][0] + bias.x;
                float c1 = acc[nt][1] + bias.y;
                float c2 = acc[nt][2] + bias.x;
                float c3 = acc[nt][3] + bias.y;
                const int base = ((nt >> 1) * 4 + tig) * (KTHS * 2) + (nt & 1);
                KThw[base + row0 * 2] = packh2(__floats2half2_rn(c0, c1));
                KThw[base + row1 * 2] = packh2(__floats2half2_rn(c2, c3));
            }
        } else {
            // Q: bias, x0.125, pack to score A-fragments in registers
            #pragma unroll
            for (int nt = 0; nt < 8; nt++) {
                float2 bias = *(const float2*)(bb + n0 + nt * 8 + 2 * tig);
                acc[nt][0] = (acc[nt][0] + bias.x) * 0.125f;
                acc[nt][1] = (acc[nt][1] + bias.y) * 0.125f;
                acc[nt][2] = (acc[nt][2] + bias.x) * 0.125f;
                acc[nt][3] = (acc[nt][3] + bias.y) * 0.125f;
            }
            #pragma unroll
            for (int ks = 0; ks < 4; ks++) {
                qa[ks][0] = packh2(__floats2half2_rn(acc[2*ks  ][0], acc[2*ks  ][1]));
                qa[ks][1] = packh2(__floats2half2_rn(acc[2*ks  ][2], acc[2*ks  ][3]));
                qa[ks][2] = packh2(__floats2half2_rn(acc[2*ks+1][0], acc[2*ks+1][1]));
                qa[ks][3] = packh2(__floats2half2_rn(acc[2*ks+1][2], acc[2*ks+1][3]));
            }
        }
    }
    __syncthreads();   // K/V stores visible; xs dead

    // ---- repack Vsp -> Vp2 (PV B-operand: 4-key packs per dim) ----
    for (int i = tid; i < 44 * HD; i += 352) {
        const int r = i >> 6, d = i & 63;          // r = c*4 + tg
        const int c = r >> 2, tg = r & 3;
        const int k0 = 16 * c + 2 * tg;            // keys k0,k0+1,k0+8,k0+9
        const int dh = d >> 1, sel = d & 1;
        __half v0 = geth(Vsp[(k0    ) * VSP_STRIDE + dh], sel);
        __half v1 = geth(Vsp[(k0 + 1) * VSP_STRIDE + dh], sel);
        __half v2 = geth(Vsp[(k0 + 8) * VSP_STRIDE + dh], sel);
        __half v3 = geth(Vsp[(k0 + 9) * VSP_STRIDE + dh], sel);
        uint2 pk;
        pk.x = packh2(__halves2half2(v0, v1));
        pk.y = packh2(__halves2half2(v2, v3));
        Vp2[r * VP2S + d] = pk;
    }
    __syncthreads();

    // ---- Phase 2: attention ----
    const int f0 = row0 / 22;
    const int f1 = row1 / 22;

    float o[8][4];
    #pragma unroll
    for (int nt = 0; nt < 8; nt++)
        #pragma unroll
        for (int i = 0; i < 4; i++) o[nt][i] = 0.f;

    float sum0 = 0.f, sum1 = 0.f;

    #pragma unroll
    for (int c = 0; c < 11; c++) {
        float s0[4] = {0.f, 0.f, 0.f, 0.f};
        float s1[4] = {0.f, 0.f, 0.f, 0.f};
        #pragma unroll
        for (int ks = 0; ks < 4; ks++) {
            const uint2* kr = KTh + (ks * 4 + tig) * KTHS + 16 * c + gid;
            uint2 kb0 = kr[0];
            uint2 kb1 = kr[8];
            mma_f16(s0, qa[ks][0], qa[ks][1], qa[ks][2], qa[ks][3], kb0.x, kb0.y);
            mma_f16(s1, qa[ks][0], qa[ks][1], qa[ks][2], qa[ks][3], kb1.x, kb1.y);
        }

        const int ca = 16 * c + 2 * tig;
        const int cb = ca + 1, cc = ca + 8, cd = ca + 9;
        const int fa = ca / 22, fb = cb / 22, fc = cc / 22, fd = cd / 22;

        float e00 = __expf((fa == f0 && ca != row0) ? NEGV : s0[0]);
        float e01 = __expf((fb == f0 && cb != row0) ? NEGV : s0[1]);
        float e02 = __expf((fa == f1 && ca != row1) ? NEGV : s0[2]);
        float e03 = __expf((fb == f1 && cb != row1) ? NEGV : s0[3]);
        float e10 = __expf((fc == f0 && cc != row0) ? NEGV : s1[0]);
        float e11 = __expf((fd == f0 && cd != row0) ? NEGV : s1[1]);
        float e12 = __expf((fc == f1 && cc != row1) ? NEGV : s1[2]);
        float e13 = __expf((fd == f1 && cd != row1) ? NEGV : s1[3]);

        sum0 += (e00 + e01) + (e10 + e11);
        sum1 += (e02 + e03) + (e12 + e13);

        unsigned a0 = packh2(__floats2half2_rn(e00, e01));
        unsigned a1 = packh2(__floats2half2_rn(e02, e03));
        unsigned a2 = packh2(__floats2half2_rn(e10, e11));
        unsigned a3 = packh2(__floats2half2_rn(e12, e13));

        const uint2* vrow = Vp2 + (c * 4 + tig) * VP2S + gid;
        #pragma unroll
        for (int nt = 0; nt < 8; nt++) {
            uint2 bf = vrow[nt * 8];
            mma_f16(o[nt], a0, a1, a2, a3, bf.x, bf.y);
        }
    }

    sum0 += __shfl_xor_sync(0xffffffffu, sum0, 1);
    sum0 += __shfl_xor_sync(0xffffffffu, sum0, 2);
    sum1 += __shfl_xor_sync(0xffffffffu, sum1, 1);
    sum1 += __shfl_xor_sync(0xffffffffu, sum1, 2);
    const float inv0 = 1.0f / sum0;
    const float inv1 = 1.0f / sum1;

    const size_t obase = (size_t)b * SEQ * DMODEL + (size_t)h * HD;
    #pragma unroll
    for (int nt = 0; nt < 8; nt++) {
        const int d = nt * 8 + 2 * tig;
        float2 r0v; r0v.x = o[nt][0] * inv0; r0v.y = o[nt][1] * inv0;
        float2 r1v; r1v.x = o[nt][2] * inv1; r1v.y = o[nt][3] * inv1;
        *(float2*)(out + obase + (size_t)row0 * DMODEL + d) = r0v;
        *(float2*)(out + obase + (size_t)row1 * DMODEL + d) = r1v;
    }
}

// ---------------------------------------------------------------------------
extern "C" void kernel_launch(void* const* d_in, const int* in_sizes, int n_in,
                              void* d_out, int out_size)
{
    const float* x  = (const float*)d_in[0];
    const float* Wq = (const float*)d_in[1];
    const float* bq = (const float*)d_in[2];
    const float* Wk = (const float*)d_in[3];
    const float* bk = (const float*)d_in[4];
    const float* Wv = (const float*)d_in[5];
    const float* bv = (const float*)d_in[6];
    float* out = (float*)d_out;

    cudaFuncSetAttribute(fused_attn_kernel,
                         cudaFuncAttributeMaxDynamicSharedMemorySize, SMEM_TOTAL);

    fused_attn_kernel<<<BATCH * NH, 352, SMEM_TOTAL>>>(x, Wq, bq, Wk, bk, Wv, bv, out);
}